// round 2
// baseline (speedup 1.0000x reference)
#include <cuda_runtime.h>

#define NN 50000
#define TOPK 32
#define INC 128
#define OUTC 64
#define BN_EPS 1e-5f

// scratch (static __device__: allocation-free per harness rules)
__device__ float g_xlin[NN * OUTC];
__device__ float g_ai[NN];
__device__ float g_aj[NN];
__device__ float g_bnsum[OUTC];
__device__ float g_bnsq[OUTC];
__device__ int   g_idx64;

// ---------------------------------------------------------------------------
// Kernel 1: x_lin = x @ W^T  (one node per thread, W^T staged in shared),
// plus per-node attention scalars a_i / a_j, BN accumulator zeroing and
// index-width detection.
// ---------------------------------------------------------------------------
__global__ __launch_bounds__(128) void k1_gemm(
    const float* __restrict__ x, const float* __restrict__ emb,
    const float* __restrict__ lin_w,
    const float* __restrict__ att_i, const float* __restrict__ att_j,
    const float* __restrict__ att_em_i, const float* __restrict__ att_em_j,
    const void* __restrict__ eidx)
{
    __shared__ float sW[INC * OUTC];          // sW[k*64 + c] = W[c][k]
    __shared__ float s_ai[OUTC], s_aj[OUTC], s_emi[OUTC], s_emj[OUTC];

    const int tid = threadIdx.x;
    for (int i = tid; i < INC * OUTC; i += 128) {
        int c = i / INC, k = i % INC;         // coalesced read of lin_w
        sW[k * OUTC + c] = lin_w[i];
    }
    if (tid < OUTC) {
        s_ai[tid]  = att_i[tid];    s_aj[tid]  = att_j[tid];
        s_emi[tid] = att_em_i[tid]; s_emj[tid] = att_em_j[tid];
    }
    if (blockIdx.x == 0) {
        if (tid < OUTC) { g_bnsum[tid] = 0.f; g_bnsq[tid] = 0.f; }
        if (tid == 0) {
            // int64 data has zero high words (all indices < 50000);
            // int32 data has words[1,3,5,7] = src[1,3,5,7] >= 1 always.
            const unsigned* w = (const unsigned*)eidx;
            g_idx64 = ((w[1] | w[3] | w[5] | w[7]) == 0u) ? 1 : 0;
        }
    }
    __syncthreads();

    const int n  = blockIdx.x * 128 + tid;
    const int ne = (n < NN) ? n : (NN - 1);
    const float4* xr = (const float4*)x + (size_t)ne * (INC / 4);

    float4 acc[16];
    #pragma unroll
    for (int i = 0; i < 16; ++i) acc[i] = make_float4(0.f, 0.f, 0.f, 0.f);

    const float4* sW4 = (const float4*)sW;
    #pragma unroll 1
    for (int k4 = 0; k4 < INC / 4; ++k4) {
        float4 xv = xr[k4];
        #pragma unroll
        for (int j = 0; j < 4; ++j) {
            float xs = (j == 0) ? xv.x : (j == 1) ? xv.y : (j == 2) ? xv.z : xv.w;
            const float4* wrow = sW4 + (k4 * 4 + j) * (OUTC / 4);
            #pragma unroll
            for (int c4 = 0; c4 < 16; ++c4) {
                float4 w = wrow[c4];
                acc[c4].x += xs * w.x;
                acc[c4].y += xs * w.y;
                acc[c4].z += xs * w.z;
                acc[c4].w += xs * w.w;
            }
        }
    }

    if (n < NN) {
        float ai = 0.f, aj = 0.f;
        float4* xo = (float4*)g_xlin + (size_t)n * 16;
        const float4* er = (const float4*)emb + (size_t)n * 16;
        #pragma unroll
        for (int c4 = 0; c4 < 16; ++c4) {
            float4 a = acc[c4];
            xo[c4] = a;
            float4 e = er[c4];
            int c = c4 * 4;
            ai += a.x * s_ai[c]     + a.y * s_ai[c + 1]
                + a.z * s_ai[c + 2] + a.w * s_ai[c + 3];
            ai += e.x * s_emi[c]     + e.y * s_emi[c + 1]
                + e.z * s_emi[c + 2] + e.w * s_emi[c + 3];
            aj += a.x * s_aj[c]     + a.y * s_aj[c + 1]
                + a.z * s_aj[c + 2] + a.w * s_aj[c + 3];
            aj += e.x * s_emj[c]     + e.y * s_emj[c + 1]
                + e.z * s_emj[c + 2] + e.w * s_emj[c + 3];
        }
        g_ai[n] = ai;
        g_aj[n] = aj;
    }
}

// ---------------------------------------------------------------------------
// Kernel 2: one warp per node — segment softmax over 32 edges + self loop,
// weighted gather-aggregate of x_lin rows, bias, and BN partial sums.
// ---------------------------------------------------------------------------
__global__ __launch_bounds__(256) void k2_aggr(
    const void* __restrict__ eidx, const float* __restrict__ bias,
    float* __restrict__ out)
{
    __shared__ float s_w[8][33];
    __shared__ int   s_s[8][33];
    __shared__ float s_red[8][OUTC];
    __shared__ float s_red2[8][OUTC];

    const int tid  = threadIdx.x;
    const int wid  = tid >> 5;
    const int lane = tid & 31;
    const int n    = blockIdx.x * 8 + wid;
    const int e    = n * TOPK + lane;

    int src;
    if (g_idx64) src = (int)((const long long*)eidx)[e];
    else         src = ((const int*)eidx)[e];

    const float ain = g_ai[n];
    float al = ain + g_aj[src];
    al = (al >= 0.f) ? al : 0.2f * al;
    float as = ain + g_aj[n];
    as = (as >= 0.f) ? as : 0.2f * as;

    // warp max over 33 logits
    float m = al;
    #pragma unroll
    for (int o = 16; o > 0; o >>= 1) m = fmaxf(m, __shfl_xor_sync(0xffffffffu, m, o));
    m = fmaxf(m, as);

    float w  = __expf(al - m);
    float ws = __expf(as - m);
    float sum = w;
    #pragma unroll
    for (int o = 16; o > 0; o >>= 1) sum += __shfl_xor_sync(0xffffffffu, sum, o);
    const float inv = 1.f / (sum + ws + 1e-16f);

    s_w[wid][lane] = w;
    s_s[wid][lane] = src;
    if (lane == 0) { s_w[wid][32] = ws; s_s[wid][32] = n; }
    __syncwarp();

    const float2* xl = (const float2*)g_xlin;
    float2 acc = make_float2(0.f, 0.f);
    #pragma unroll 8
    for (int k = 0; k < 33; ++k) {
        float we = s_w[wid][k];
        int   s  = s_s[wid][k];
        float2 v = xl[(size_t)s * 32 + lane];
        acc.x += we * v.x;
        acc.y += we * v.y;
    }

    float2 b = ((const float2*)bias)[lane];
    float2 r;
    r.x = acc.x * inv + b.x;
    r.y = acc.y * inv + b.y;
    ((float2*)out)[(size_t)n * 32 + lane] = r;

    // block-level BN partial sums (no shared atomics)
    s_red [wid][2 * lane]     = r.x;
    s_red [wid][2 * lane + 1] = r.y;
    s_red2[wid][2 * lane]     = r.x * r.x;
    s_red2[wid][2 * lane + 1] = r.y * r.y;
    __syncthreads();

    if (tid < OUTC) {
        float t = 0.f;
        #pragma unroll
        for (int ww = 0; ww < 8; ++ww) t += s_red[ww][tid];
        atomicAdd(&g_bnsum[tid], t);
    } else if (tid < 2 * OUTC) {
        const int c = tid - OUTC;
        float t = 0.f;
        #pragma unroll
        for (int ww = 0; ww < 8; ++ww) t += s_red2[ww][c];
        atomicAdd(&g_bnsq[c], t);
    }
}

// ---------------------------------------------------------------------------
// Kernel 3: BatchNorm (training-mode batch stats, biased var) + ReLU, in place.
// ---------------------------------------------------------------------------
__global__ __launch_bounds__(256) void k3_bn(
    float* __restrict__ out,
    const float* __restrict__ gamma, const float* __restrict__ beta)
{
    const int i = blockIdx.x * 256 + threadIdx.x;      // over float4s
    if (i >= NN * OUTC / 4) return;
    const int c0 = (i & 15) * 4;                       // 16 float4s per node
    float4 v = ((const float4*)out)[i];
    const float invN = 1.0f / (float)NN;
    float vv[4] = {v.x, v.y, v.z, v.w};
    float rr[4];
    #pragma unroll
    for (int j = 0; j < 4; ++j) {
        int c = c0 + j;
        float mu  = g_bnsum[c] * invN;
        float var = g_bnsq[c] * invN - mu * mu;
        float sc  = gamma[c] * rsqrtf(var + BN_EPS);
        float sh  = beta[c] - mu * sc;
        rr[j] = fmaxf(vv[j] * sc + sh, 0.f);
    }
    ((float4*)out)[i] = make_float4(rr[0], rr[1], rr[2], rr[3]);
}

// ---------------------------------------------------------------------------
extern "C" void kernel_launch(void* const* d_in, const int* in_sizes, int n_in,
                              void* d_out, int out_size)
{
    const float* x     = (const float*)d_in[0];
    const float* emb   = (const float*)d_in[1];
    const void*  ei    = d_in[2];
    const float* lw    = (const float*)d_in[3];
    const float* atti  = (const float*)d_in[4];
    const float* attj  = (const float*)d_in[5];
    const float* atemi = (const float*)d_in[6];
    const float* atemj = (const float*)d_in[7];
    const float* bias  = (const float*)d_in[8];
    const float* gamma = (const float*)d_in[9];
    const float* beta  = (const float*)d_in[10];
    float* out = (float*)d_out;

    k1_gemm<<<(NN + 127) / 128, 128>>>(x, emb, lw, atti, attj, atemi, atemj, ei);
    k2_aggr<<<NN / 8, 256>>>(ei, bias, out);
    k3_bn<<<(NN * OUTC / 4 + 255) / 256, 256>>>(out, gamma, beta);
}